// round 15
// baseline (speedup 1.0000x reference)
#include <cuda_runtime.h>
#include <cuda_bf16.h>

// XORNet forward: 2-layer LIF spiking net (snntorch Leaky, subtract reset).
// R12 calibration: identical-code noise is +-1us ncu. Only structural slot
// cuts count. R13: halve the layer-2 dot (16 -> 8 slots/step) by ALLOCATING
// the scalar FSET outputs into lane-adjacent F2 pairs sd[h][q]:
//   - layer-1 reset FFMAs read them as scalars (pairing-agnostic), layout
//     and ILP identical to R4 (the 15.78us-ncu best);
//   - the dot runs as mul2 + 3x fma2 per lane-pair (packed, lane-wise RN,
//     binary-spike products exact, same k-order -> bit-identical);
//   - packed o2[q] feeds layer-2 add2 directly (deletes make_float2 MOVs).
// ~77 -> ~68 issue slots/step/thread. regs pinned <=64 via launch_bounds.
// rel_err canary = 8.596e-4 (must not move).

#define SNN_T 20
#define SNN_H 4

union F2 { float2 f; unsigned long long u; };

__device__ __forceinline__ void mul2(F2& d, const F2& a, const F2& b) {
    asm("mul.rn.f32x2 %0, %1, %2;" : "=l"(d.u) : "l"(a.u), "l"(b.u));
}
__device__ __forceinline__ void add2(F2& d, const F2& a, const F2& b) {
    asm("add.rn.f32x2 %0, %1, %2;" : "=l"(d.u) : "l"(a.u), "l"(b.u));
}
__device__ __forceinline__ void fma2(F2& d, const F2& a, const F2& b, const F2& c) {
    asm("fma.rn.f32x2 %0, %1, %2, %3;" : "=l"(d.u) : "l"(a.u), "l"(b.u), "l"(c.u));
}
// 1.0f if a > b else 0.0f, single SASS FSET
__device__ __forceinline__ float fset_gt(float a, float b) {
    float r;
    asm("set.gt.f32.f32 %0, %1, %2;" : "=f"(r) : "f"(a), "f"(b));
    return r;
}

__global__ __launch_bounds__(256, 4) void xornet_snn_kernel(
    const float* __restrict__ x,    // [B, 2]
    const float* __restrict__ w1,   // [4, 2]
    const float* __restrict__ w2,   // [1, 4]
    float* __restrict__ out,        // [T, B, 1]
    int B)
{
    const int i = blockIdx.x * blockDim.x + threadIdx.x;  // handles b = 4i..4i+3
    if (i * 4 >= B) return;
    const int Bq = B >> 2;

    // Broadcast weights (L2/L1 hit after first warp).
    float w1r0[SNN_H], w1r1[SNN_H];
    F2 w2b[SNN_H];
#pragma unroll
    for (int h = 0; h < SNN_H; h++) {
        w1r0[h] = __ldg(&w1[2 * h]);
        w1r1[h] = __ldg(&w1[2 * h + 1]);
        const float w = __ldg(&w2[h]);
        w2b[h].f = make_float2(w, w);
    }

    // x for 4 batch elements: 2x float4.
    const float4 xa = __ldg(&((const float4*)x)[2 * i]);
    const float4 xb = __ldg(&((const float4*)x)[2 * i + 1]);
    const float x0[4] = {xa.x, xa.z, xb.x, xb.z};
    const float x1[4] = {xa.y, xa.w, xb.y, xb.w};

    // cur[l][p] packs neurons (2p, 2p+1) for batch lane l (k-ascending fma dot).
    F2 cur[4][2];
#pragma unroll
    for (int l = 0; l < 4; l++)
#pragma unroll
        for (int p = 0; p < 2; p++) {
            cur[l][p].f.x = fmaf(x1[l], w1r1[2 * p],     __fmul_rn(x0[l], w1r0[2 * p]));
            cur[l][p].f.y = fmaf(x1[l], w1r1[2 * p + 1], __fmul_rn(x0[l], w1r0[2 * p + 1]));
        }

    F2 c09; c09.f = make_float2(0.9f, 0.9f);

    // State: m1 packed per neuron-pair within a lane (R4 layout, full ILP);
    // spikes sd[h][q] packed per LANE-pair (lanes 2q, 2q+1) for neuron h,
    // so the dot can run packed without any assembly MOVs.
    F2 m1[4][2];
    F2 sd[SNN_H][2];
    F2 m2p[2];        // layer-2 membranes, lane pairs (0,1) and (2,3)
    float s2[4];
#pragma unroll
    for (int l = 0; l < 4; l++)
#pragma unroll
        for (int p = 0; p < 2; p++) m1[l][p].u = 0ull;
#pragma unroll
    for (int h = 0; h < SNN_H; h++) { sd[h][0].u = 0ull; sd[h][1].u = 0ull; }
    m2p[0].u = 0ull; m2p[1].u = 0ull;
    s2[0] = s2[1] = s2[2] = s2[3] = 0.0f;

#pragma unroll
    for (int t = 0; t < SNN_T; t++) {
        // ── layer-1: R4 dataflow; spikes written into lane-pair slots ──
#pragma unroll
        for (int l = 0; l < 4; l++) {
            const int q = l >> 1;
            const bool hi = (l & 1);
#pragma unroll
            for (int p = 0; p < 2; p++) {
                // previous spikes of neurons 2p, 2p+1 for this lane (scalars)
                const float sa = hi ? sd[2 * p][q].f.y     : sd[2 * p][q].f.x;
                const float sb = hi ? sd[2 * p + 1][q].f.y : sd[2 * p + 1][q].f.x;
                F2 mm;
                mul2(mm, m1[l][p], c09);          // 0.9*m   (packed RN)
                add2(mm, mm, cur[l][p]);          // + cur   (packed RN)
                mm.f.x = fmaf(sa, -1.0f, mm.f.x); // - reset (== sub for s in {0,1})
                mm.f.y = fmaf(sb, -1.0f, mm.f.y);
                m1[l][p] = mm;
                const float na = fset_gt(mm.f.x, 1.0f);   // spike = (m > 1)
                const float nb = fset_gt(mm.f.y, 1.0f);
                if (hi) { sd[2 * p][q].f.y = na; sd[2 * p + 1][q].f.y = nb; }
                else    { sd[2 * p][q].f.x = na; sd[2 * p + 1][q].f.x = nb; }
            }
        }
        // ── dot + layer-2, packed per lane-pair ──
        float4 ov;
#pragma unroll
        for (int q = 0; q < 2; q++) {
            // spk1 @ w2^T for lanes (2q, 2q+1): binary s -> exact products,
            // k-ascending chain, lane-wise identical to scalar fma chain.
            F2 o;
            mul2(o, sd[0][q], w2b[0]);
            fma2(o, sd[1][q], w2b[1], o);
            fma2(o, sd[2][q], w2b[2], o);
            fma2(o, sd[3][q], w2b[3], o);
            // layer-2 LIF
            F2 mm;
            mul2(mm, m2p[q], c09);
            add2(mm, mm, o);
            mm.f.x = fmaf(s2[2 * q],     -1.0f, mm.f.x);
            mm.f.y = fmaf(s2[2 * q + 1], -1.0f, mm.f.y);
            m2p[q] = mm;
            s2[2 * q]     = fset_gt(mm.f.x, 1.0f);
            s2[2 * q + 1] = fset_gt(mm.f.y, 1.0f);
        }
        ov.x = s2[0]; ov.y = s2[1]; ov.z = s2[2]; ov.w = s2[3];
        ((float4*)out)[(size_t)t * Bq + i] = ov;   // immediate-offset STG.128
    }
}

extern "C" void kernel_launch(void* const* d_in, const int* in_sizes, int n_in,
                              void* d_out, int out_size)
{
    const float* x  = (const float*)d_in[0];   // [B, 2]
    const float* w1 = (const float*)d_in[1];   // [4, 2]
    const float* w2 = (const float*)d_in[2];   // [1, 4]
    float* out = (float*)d_out;                // [T, B, 1]

    const int B = in_sizes[0] / 2;             // 1,048,576
    const int threads = 256;
    const int nthreads = B / 4;                // one thread per 4 batch elems
    const int blocks = (nthreads + threads - 1) / threads;

    xornet_snn_kernel<<<blocks, threads>>>(x, w1, w2, out, B);
}

// round 16
// speedup vs baseline: 1.0394x; 1.0394x over previous
#include <cuda_runtime.h>
#include <cuda_bf16.h>

// XORNet forward: 2-layer LIF spiking net (snntorch Leaky, subtract reset).
// Plateau analysis (R4..R13): ncu dur pinned at 15.8-16.6us across a 30%
// issue-slot swing -> not purely issue-bound. Last untested axis: I-cache.
// Fully-unrolled T=20 body = ~22KB SASS (3.7x the 6KB L0). R15 = R13 body
// (fewest slots: lane-pair spike allocation -> packed mul2+3xfma2 dot) with
// the T-loop rolled to unroll-4: 5 trips x ~4.5KB body fits L0 entirely.
// Loop overhead ~15 cyc/trip, amortized. Per-element op sequence unchanged:
//   m = ((0.9*m) + cur) - s_prev ; s = (m > 1) ; o = k-ascending fma dot.
// rel_err canary = 8.596e-4 (must not move).

#define SNN_T 20
#define SNN_H 4

union F2 { float2 f; unsigned long long u; };

__device__ __forceinline__ void mul2(F2& d, const F2& a, const F2& b) {
    asm("mul.rn.f32x2 %0, %1, %2;" : "=l"(d.u) : "l"(a.u), "l"(b.u));
}
__device__ __forceinline__ void add2(F2& d, const F2& a, const F2& b) {
    asm("add.rn.f32x2 %0, %1, %2;" : "=l"(d.u) : "l"(a.u), "l"(b.u));
}
__device__ __forceinline__ void fma2(F2& d, const F2& a, const F2& b, const F2& c) {
    asm("fma.rn.f32x2 %0, %1, %2, %3;" : "=l"(d.u) : "l"(a.u), "l"(b.u), "l"(c.u));
}
// 1.0f if a > b else 0.0f, single SASS FSET
__device__ __forceinline__ float fset_gt(float a, float b) {
    float r;
    asm("set.gt.f32.f32 %0, %1, %2;" : "=f"(r) : "f"(a), "f"(b));
    return r;
}

__global__ __launch_bounds__(256, 4) void xornet_snn_kernel(
    const float* __restrict__ x,    // [B, 2]
    const float* __restrict__ w1,   // [4, 2]
    const float* __restrict__ w2,   // [1, 4]
    float* __restrict__ out,        // [T, B, 1]
    int B)
{
    const int i = blockIdx.x * blockDim.x + threadIdx.x;  // handles b = 4i..4i+3
    if (i * 4 >= B) return;
    const int Bq = B >> 2;

    // Broadcast weights (L2/L1 hit after first warp).
    float w1r0[SNN_H], w1r1[SNN_H];
    F2 w2b[SNN_H];
#pragma unroll
    for (int h = 0; h < SNN_H; h++) {
        w1r0[h] = __ldg(&w1[2 * h]);
        w1r1[h] = __ldg(&w1[2 * h + 1]);
        const float w = __ldg(&w2[h]);
        w2b[h].f = make_float2(w, w);
    }

    // x for 4 batch elements: 2x float4.
    const float4 xa = __ldg(&((const float4*)x)[2 * i]);
    const float4 xb = __ldg(&((const float4*)x)[2 * i + 1]);
    const float x0[4] = {xa.x, xa.z, xb.x, xb.z};
    const float x1[4] = {xa.y, xa.w, xb.y, xb.w};

    // cur[l][p] packs neurons (2p, 2p+1) for batch lane l (k-ascending fma dot).
    F2 cur[4][2];
#pragma unroll
    for (int l = 0; l < 4; l++)
#pragma unroll
        for (int p = 0; p < 2; p++) {
            cur[l][p].f.x = fmaf(x1[l], w1r1[2 * p],     __fmul_rn(x0[l], w1r0[2 * p]));
            cur[l][p].f.y = fmaf(x1[l], w1r1[2 * p + 1], __fmul_rn(x0[l], w1r0[2 * p + 1]));
        }

    F2 c09; c09.f = make_float2(0.9f, 0.9f);

    // State: m1 packed per neuron-pair within a lane (full ILP, R4 layout);
    // spikes sd[h][q] packed per LANE-pair so the dot runs packed, MOV-free.
    F2 m1[4][2];
    F2 sd[SNN_H][2];
    F2 m2p[2];        // layer-2 membranes, lane pairs (0,1) and (2,3)
    float s2[4];
#pragma unroll
    for (int l = 0; l < 4; l++)
#pragma unroll
        for (int p = 0; p < 2; p++) m1[l][p].u = 0ull;
#pragma unroll
    for (int h = 0; h < SNN_H; h++) { sd[h][0].u = 0ull; sd[h][1].u = 0ull; }
    m2p[0].u = 0ull; m2p[1].u = 0ull;
    s2[0] = s2[1] = s2[2] = s2[3] = 0.0f;

    // Rolled T-loop: unroll-4 -> 5 trips, ~4.5KB body fits the 6KB L0 I$.
#pragma unroll 4
    for (int t = 0; t < SNN_T; t++) {
        // ── layer-1: R4 dataflow; spikes written into lane-pair slots ──
#pragma unroll
        for (int l = 0; l < 4; l++) {
            const int q = l >> 1;
            const bool hi = (l & 1);
#pragma unroll
            for (int p = 0; p < 2; p++) {
                const float sa = hi ? sd[2 * p][q].f.y     : sd[2 * p][q].f.x;
                const float sb = hi ? sd[2 * p + 1][q].f.y : sd[2 * p + 1][q].f.x;
                F2 mm;
                mul2(mm, m1[l][p], c09);          // 0.9*m   (packed RN)
                add2(mm, mm, cur[l][p]);          // + cur   (packed RN)
                mm.f.x = fmaf(sa, -1.0f, mm.f.x); // - reset (== sub for s in {0,1})
                mm.f.y = fmaf(sb, -1.0f, mm.f.y);
                m1[l][p] = mm;
                const float na = fset_gt(mm.f.x, 1.0f);   // spike = (m > 1)
                const float nb = fset_gt(mm.f.y, 1.0f);
                if (hi) { sd[2 * p][q].f.y = na; sd[2 * p + 1][q].f.y = nb; }
                else    { sd[2 * p][q].f.x = na; sd[2 * p + 1][q].f.x = nb; }
            }
        }
        // ── dot + layer-2, packed per lane-pair ──
        float4 ov;
#pragma unroll
        for (int q = 0; q < 2; q++) {
            F2 o;
            mul2(o, sd[0][q], w2b[0]);            // binary s -> exact products,
            fma2(o, sd[1][q], w2b[1], o);         // k-ascending chain
            fma2(o, sd[2][q], w2b[2], o);
            fma2(o, sd[3][q], w2b[3], o);
            F2 mm;
            mul2(mm, m2p[q], c09);
            add2(mm, mm, o);
            mm.f.x = fmaf(s2[2 * q],     -1.0f, mm.f.x);
            mm.f.y = fmaf(s2[2 * q + 1], -1.0f, mm.f.y);
            m2p[q] = mm;
            s2[2 * q]     = fset_gt(mm.f.x, 1.0f);
            s2[2 * q + 1] = fset_gt(mm.f.y, 1.0f);
        }
        ov.x = s2[0]; ov.y = s2[1]; ov.z = s2[2]; ov.w = s2[3];
        ((float4*)out)[(size_t)t * Bq + i] = ov;   // STG.128, strength-reduced idx
    }
}

extern "C" void kernel_launch(void* const* d_in, const int* in_sizes, int n_in,
                              void* d_out, int out_size)
{
    const float* x  = (const float*)d_in[0];   // [B, 2]
    const float* w1 = (const float*)d_in[1];   // [4, 2]
    const float* w2 = (const float*)d_in[2];   // [1, 4]
    float* out = (float*)d_out;                // [T, B, 1]

    const int B = in_sizes[0] / 2;             // 1,048,576
    const int threads = 256;
    const int nthreads = B / 4;                // one thread per 4 batch elems
    const int blocks = (nthreads + threads - 1) / threads;

    xornet_snn_kernel<<<blocks, threads>>>(x, w1, w2, out, B);
}